// round 13
// baseline (speedup 1.0000x reference)
#include <cuda_runtime.h>
#include <stdint.h>

#define BATCH  4
#define NPTS   64
#define DIM    128
#define NFULL  (NPTS*NPTS)     // 4096
#define NPRED  2016            // classes (i<j)
#define GRID_P 128             // (b, t, slice s of 126 rows)
#define GRID_L 1008            // (b, 252 groups of 4 row-pairs x 2 parity warps)

__device__ float g_rn[BATCH*2*NPRED];            // [b][t][l] inverse norms
__device__ float g_C [(size_t)BATCH*2*NPRED*64]; // [b][t][k][p] scaled diff rows
__device__ double g_acc;
__device__ unsigned int g_done;

// ---------------------------------------------------------------- kernel 1
// Grid 128 = (b, t, s16). Compute the 64x64 Gram G for (b,t) in-register from
// the raw inputs (4 d-slices), then rn + C rows for slice s (126 k-rows).
__global__ __launch_bounds__(256) void prep_k(const float* __restrict__ student,
                                              const float* __restrict__ teacher) {
    if (blockIdx.x == 0 && threadIdx.x == 0) { g_acc = 0.0; g_done = 0u; }
    int bid = blockIdx.x;
    int b = bid >> 5, t = (bid >> 4) & 1, s = bid & 15;
    const float* X = (t ? teacher : student) + (size_t)b * NPTS * DIM;

    __shared__ float sXT[32][67];    // transposed d-slice, padded
    __shared__ float G[64 * 64];
    __shared__ float sRNl[126];
    __shared__ int   sI[126], sJ[126];

    int tid = threadIdx.x;
    int bi = tid >> 4, bj = tid & 15;

    float acc[4][4];
    #pragma unroll
    for (int r = 0; r < 4; r++)
        #pragma unroll
        for (int c = 0; c < 4; c++) acc[r][c] = 0.f;

    for (int dq = 0; dq < 4; dq++) {
        if (dq) __syncthreads();
        for (int u = tid; u < NPTS * 32; u += 256) {
            int n = u >> 5, d = u & 31;
            sXT[d][n] = X[(size_t)n * DIM + dq * 32 + d];
        }
        __syncthreads();
        #pragma unroll 4
        for (int d = 0; d < 32; d++) {
            float xi[4], xj[4];
            #pragma unroll
            for (int r = 0; r < 4; r++) xi[r] = sXT[d][bi * 4 + r];
            #pragma unroll
            for (int c = 0; c < 4; c++) xj[c] = sXT[d][bj * 4 + c];
            #pragma unroll
            for (int r = 0; r < 4; r++)
                #pragma unroll
                for (int c = 0; c < 4; c++) acc[r][c] += xi[r] * xj[c];
        }
    }
    #pragma unroll
    for (int r = 0; r < 4; r++)
        #pragma unroll
        for (int c = 0; c < 4; c++)
            G[(bi * 4 + r) * 64 + (bj * 4 + c)] = acc[r][c];
    __syncthreads();

    if (tid < 126) {
        int l = s * 126 + tid;
        int p = 0, rem = l;
        while (rem >= 63 - p) { rem -= 63 - p; p++; }
        int q = p + 1 + rem;
        float ss = G[p * 64 + p] - 2.f * G[p * 64 + q] + G[q * 64 + q];
        float rn = 1.f / fmaxf(sqrtf(fmaxf(ss, 0.f)), 1e-12f);
        sI[tid] = p; sJ[tid] = q; sRNl[tid] = rn;
        g_rn[(b * 2 + t) * NPRED + l] = rn;
    }
    __syncthreads();

    for (int u = tid; u < 126 * 64; u += 256) {
        int kl = u >> 6, p = u & 63;
        float val = (G[sI[kl] * 64 + p] - G[sJ[kl] * 64 + p]) * sRNl[kl];
        g_C[((size_t)(b * 2 + t) * NPRED + s * 126 + kl) * 64 + p] = val;
    }
}

// ---------------------------------------------------------------- kernel 2
// Grid 1008 = (b, c252), 256 threads (8 warps). Warp w = (pair pr, parity pa).
// Row pair {g, 2015-g}, g = c*4+pr. Masking is baked into the smem table
// sRN2[p][q] = (rns_l, rnt_l) for q>p, (0,0) otherwise -> main loop body is
// unconditional (zero rn => zero contribution). The p==i row (q>=j boundary)
// is one explicit predicated iteration on the pa==0 warp.
__global__ __launch_bounds__(256) void loss_k(float* __restrict__ out) {
    __shared__ float2 sRN2[63 * 64];         // 31.5 KB mask-baked rn table
    __shared__ float wsum[8];

    int tid = threadIdx.x, wid = tid >> 5, lane = tid & 31;
    int pr = wid >> 1, pa = wid & 1;
    int bid = blockIdx.x;
    int b = bid / 252, c = bid - b * 252;

    const float* rns = g_rn + (b * 2 + 0) * NPRED;
    const float* rnt = g_rn + (b * 2 + 1) * NPRED;
    for (int u = tid; u < 63 * 64; u += 256) {
        int p = u >> 6, q = u & 63;
        float2 v = make_float2(0.f, 0.f);
        if (q > p) {
            int l = 63 * p - ((p * (p - 1)) >> 1) + q - p - 1;
            v = make_float2(rns[l], rnt[l]);
        }
        sRN2[u] = v;
    }
    __syncthreads();

    float lsum0 = 0.f, lsum1 = 0.f;
    #pragma unroll
    for (int rr = 0; rr < 2; rr++) {
        int g = c * 4 + pr;
        int k = (rr == 0) ? g : (2015 - g);
        int i = 0, rem = k;
        while (rem >= 63 - i) { rem -= 63 - i; i++; }
        int j = i + 1 + rem;

        const float* Cs = g_C + ((size_t)(b * 2 + 0) * NPRED + k) * 64;
        const float* Ct = g_C + ((size_t)(b * 2 + 1) * NPRED + k) * 64;
        float c0x = Cs[lane], c1x = Cs[lane + 32];
        float c0y = Ct[lane], c1y = Ct[lane + 32];

        // special first row p == i: enforce q >= j (pa==0 warp only)
        if (pa == 0) {
            float sx = (i < 32) ? c0x : c1x;
            float sy = (i < 32) ? c0y : c1y;
            float cpx = __shfl_sync(0xffffffffu, sx, i & 31);
            float cpy = __shfl_sync(0xffffffffu, sy, i & 31);
            float2 rl0 = sRN2[i * 64 + lane];
            float2 rl1 = sRN2[i * 64 + 32 + lane];
            float d0 = (cpx - c0x) * rl0.x - (cpy - c0y) * rl0.y;
            float a0 = fabsf(d0), m0 = fminf(a0, 1.f);
            if (lane >= j) lsum0 += m0 * (a0 - 0.5f * m0);
            float d1 = (cpx - c1x) * rl1.x - (cpy - c1y) * rl1.y;
            float a1 = fabsf(d1), m1 = fminf(a1, 1.f);
            if (lane + 32 >= j) lsum1 += m1 * (a1 - 0.5f * m1);
        }

        // main rows p > i: fully unconditional (table-masked)
        for (int p = i + 2 - pa; p < 63; p += 2) {
            float sx = (p < 32) ? c0x : c1x;
            float sy = (p < 32) ? c0y : c1y;
            float cpx = __shfl_sync(0xffffffffu, sx, p & 31);
            float cpy = __shfl_sync(0xffffffffu, sy, p & 31);
            float2 rl0 = sRN2[p * 64 + lane];
            float2 rl1 = sRN2[p * 64 + 32 + lane];
            float d0 = (cpx - c0x) * rl0.x - (cpy - c0y) * rl0.y;
            float a0 = fabsf(d0), m0 = fminf(a0, 1.f);
            lsum0 += m0 * (a0 - 0.5f * m0);
            float d1 = (cpx - c1x) * rl1.x - (cpy - c1y) * rl1.y;
            float a1 = fabsf(d1), m1 = fminf(a1, 1.f);
            lsum1 += m1 * (a1 - 0.5f * m1);
        }
    }

    float lsum = lsum0 + lsum1;
    #pragma unroll
    for (int o = 16; o; o >>= 1) lsum += __shfl_xor_sync(0xffffffffu, lsum, o);
    if (lane == 0) wsum[wid] = lsum;
    __syncthreads();
    if (tid == 0) {
        float sblk = 0.f;
        #pragma unroll
        for (int w2 = 0; w2 < 8; w2++) sblk += wsum[w2];
        atomicAdd(&g_acc, (double)(2.0f * sblk));   // weight 2 for l>k
        __threadfence();
        unsigned int ticket = atomicAdd(&g_done, 1u);
        if (ticket == GRID_L - 1) {
            double v = *((volatile double*)&g_acc);
            out[0] = (float)(4.0 * v / ((double)BATCH * NFULL * NFULL));
        }
    }
}

extern "C" void kernel_launch(void* const* d_in, const int* in_sizes, int n_in,
                              void* d_out, int out_size) {
    const float* student = (const float*)d_in[0];
    const float* teacher = (const float*)d_in[1];
    prep_k<<<GRID_P, 256>>>(student, teacher);
    loss_k<<<GRID_L, 256>>>((float*)d_out);
}

// round 14
// speedup vs baseline: 1.3553x; 1.3553x over previous
#include <cuda_runtime.h>
#include <stdint.h>

#define BATCH  4
#define NPTS   64
#define DIM    128
#define NFULL  (NPTS*NPTS)     // 4096
#define NPRED  2016            // classes (i<j)
#define GRID_P 128             // (b, t, slice s of 126 rows)
#define GRID_L 1008            // (b, 252 groups of 8 k-rows)

__device__ float g_C [(size_t)BATCH*2*NPRED*64];      // [b][t][k][p] scaled diff rows
__device__ __align__(16) float2 g_rnTab[BATCH][64*64]; // masked (rns,rnt) table per batch
__device__ double g_acc;
__device__ unsigned int g_done;

// ---------------------------------------------------------------- kernel 1
// Grid 128 = (b, t, s16). Compute the 64x64 Gram G for (b,t) in-register from
// the raw inputs (4 d-slices), then rn + C rows for slice s (126 k-rows).
// Each CTA writes its classes' rn into component t of g_rnTab[b]; the
// (t==0, s==0) CTA zeroes the invalid (q<=p or p==63) entries.
__global__ __launch_bounds__(256) void prep_k(const float* __restrict__ student,
                                              const float* __restrict__ teacher) {
    if (blockIdx.x == 0 && threadIdx.x == 0) { g_acc = 0.0; g_done = 0u; }
    int bid = blockIdx.x;
    int b = bid >> 5, t = (bid >> 4) & 1, s = bid & 15;
    const float* X = (t ? teacher : student) + (size_t)b * NPTS * DIM;

    __shared__ float sXT[32][67];    // transposed d-slice, padded
    __shared__ float G[64 * 64];
    __shared__ float sRNl[126];
    __shared__ int   sI[126], sJ[126];

    int tid = threadIdx.x;
    int bi = tid >> 4, bj = tid & 15;

    // zero invalid table entries (disjoint from all valid writes)
    if (t == 0 && s == 0) {
        for (int u = tid; u < 64 * 64; u += 256) {
            int p = u >> 6, q = u & 63;
            if (q <= p || p == 63) g_rnTab[b][u] = make_float2(0.f, 0.f);
        }
    }

    float acc[4][4];
    #pragma unroll
    for (int r = 0; r < 4; r++)
        #pragma unroll
        for (int c = 0; c < 4; c++) acc[r][c] = 0.f;

    for (int dq = 0; dq < 4; dq++) {
        if (dq) __syncthreads();
        for (int u = tid; u < NPTS * 32; u += 256) {
            int n = u >> 5, d = u & 31;
            sXT[d][n] = X[(size_t)n * DIM + dq * 32 + d];
        }
        __syncthreads();
        #pragma unroll 4
        for (int d = 0; d < 32; d++) {
            float xi[4], xj[4];
            #pragma unroll
            for (int r = 0; r < 4; r++) xi[r] = sXT[d][bi * 4 + r];
            #pragma unroll
            for (int c = 0; c < 4; c++) xj[c] = sXT[d][bj * 4 + c];
            #pragma unroll
            for (int r = 0; r < 4; r++)
                #pragma unroll
                for (int c = 0; c < 4; c++) acc[r][c] += xi[r] * xj[c];
        }
    }
    #pragma unroll
    for (int r = 0; r < 4; r++)
        #pragma unroll
        for (int c = 0; c < 4; c++)
            G[(bi * 4 + r) * 64 + (bj * 4 + c)] = acc[r][c];
    __syncthreads();

    if (tid < 126) {
        int l = s * 126 + tid;
        int p = 0, rem = l;
        while (rem >= 63 - p) { rem -= 63 - p; p++; }
        int q = p + 1 + rem;
        float ss = G[p * 64 + p] - 2.f * G[p * 64 + q] + G[q * 64 + q];
        float rn = 1.f / fmaxf(sqrtf(fmaxf(ss, 0.f)), 1e-12f);
        sI[tid] = p; sJ[tid] = q; sRNl[tid] = rn;
        ((float*)&g_rnTab[b][p * 64 + q])[t] = rn;   // component t
    }
    __syncthreads();

    for (int u = tid; u < 126 * 64; u += 256) {
        int kl = u >> 6, p = u & 63;
        float val = (G[sI[kl] * 64 + p] - G[sJ[kl] * 64 + p]) * sRNl[kl];
        g_C[((size_t)(b * 2 + t) * NPRED + s * 126 + kl) * 64 + p] = val;
    }
}

// ---------------------------------------------------------------- kernel 2
// Grid 1008 = (b, c252), 256 threads (8 warps). Warp w owns k = c*8 + w.
// FULL-SQUARE sum: every k-row runs the constant 63-iteration p-loop over
// ALL classes l (table-masked: rn==0 for q<=p kills invalid slots). Total
// reference loss = 4 * full-square sum; no triangle logic, no weights.
__global__ __launch_bounds__(256) void loss_k(float* __restrict__ out) {
    __shared__ __align__(16) float2 sRN2[64 * 64];   // 32 KB masked rn table
    __shared__ float wsum[8];

    int tid = threadIdx.x, wid = tid >> 5, lane = tid & 31;
    int bid = blockIdx.x;
    int b = bid / 252, c = bid - b * 252;

    // branchless vectorized table copy (L2-resident source)
    {
        const float4* src = (const float4*)g_rnTab[b];
        float4* dst = (float4*)sRN2;
        #pragma unroll
        for (int u = 0; u < 8; u++) dst[tid + u * 256] = src[tid + u * 256];
    }
    __syncthreads();

    int k = c * 8 + wid;
    const float* Cs = g_C + ((size_t)(b * 2 + 0) * NPRED + k) * 64;
    const float* Ct = g_C + ((size_t)(b * 2 + 1) * NPRED + k) * 64;
    float c0x = Cs[lane], c1x = Cs[lane + 32];
    float c0y = Ct[lane], c1y = Ct[lane + 32];

    float lsum0 = 0.f, lsum1 = 0.f;
    #pragma unroll
    for (int p = 0; p < 32; p++) {
        float cpx = __shfl_sync(0xffffffffu, c0x, p);
        float cpy = __shfl_sync(0xffffffffu, c0y, p);
        float2 rl0 = sRN2[p * 64 + lane];
        float2 rl1 = sRN2[p * 64 + 32 + lane];
        float e0 = cpx - c0x, f0 = cpy - c0y;
        float d0 = e0 * rl0.x - f0 * rl0.y;
        float a0 = fabsf(d0), m0 = fminf(a0, 1.f);
        lsum0 += m0 * (a0 - 0.5f * m0);
        float e1 = cpx - c1x, f1 = cpy - c1y;
        float d1 = e1 * rl1.x - f1 * rl1.y;
        float a1 = fabsf(d1), m1 = fminf(a1, 1.f);
        lsum1 += m1 * (a1 - 0.5f * m1);
    }
    #pragma unroll
    for (int p = 32; p < 63; p++) {
        float cpx = __shfl_sync(0xffffffffu, c1x, p - 32);
        float cpy = __shfl_sync(0xffffffffu, c1y, p - 32);
        float2 rl0 = sRN2[p * 64 + lane];
        float2 rl1 = sRN2[p * 64 + 32 + lane];
        float e0 = cpx - c0x, f0 = cpy - c0y;
        float d0 = e0 * rl0.x - f0 * rl0.y;
        float a0 = fabsf(d0), m0 = fminf(a0, 1.f);
        lsum0 += m0 * (a0 - 0.5f * m0);
        float e1 = cpx - c1x, f1 = cpy - c1y;
        float d1 = e1 * rl1.x - f1 * rl1.y;
        float a1 = fabsf(d1), m1 = fminf(a1, 1.f);
        lsum1 += m1 * (a1 - 0.5f * m1);
    }

    float lsum = lsum0 + lsum1;
    #pragma unroll
    for (int o = 16; o; o >>= 1) lsum += __shfl_xor_sync(0xffffffffu, lsum, o);
    if (lane == 0) wsum[wid] = lsum;
    __syncthreads();
    if (tid == 0) {
        float sblk = 0.f;
        #pragma unroll
        for (int w2 = 0; w2 < 8; w2++) sblk += wsum[w2];
        atomicAdd(&g_acc, (double)sblk);
        __threadfence();
        unsigned int ticket = atomicAdd(&g_done, 1u);
        if (ticket == GRID_L - 1) {
            double v = *((volatile double*)&g_acc);
            out[0] = (float)(4.0 * v / ((double)BATCH * NFULL * NFULL));
        }
    }
}

extern "C" void kernel_launch(void* const* d_in, const int* in_sizes, int n_in,
                              void* d_out, int out_size) {
    const float* student = (const float*)d_in[0];
    const float* teacher = (const float*)d_in[1];
    prep_k<<<GRID_P, 256>>>(student, teacher);
    loss_k<<<GRID_L, 256>>>((float*)d_out);
}

// round 15
// speedup vs baseline: 1.3703x; 1.0111x over previous
#include <cuda_runtime.h>
#include <stdint.h>

#define BATCH  4
#define NPTS   64
#define DIM    128
#define NFULL  (NPTS*NPTS)     // 4096
#define NPRED  2016            // classes (i<j)
#define GRID_P 128             // (b, t, slice s of 126 rows)
#define GRID_L 504             // (b, 126 groups of 16 k-rows)

__device__ float g_C [(size_t)BATCH*2*NPRED*64];        // [b][t][k][p] scaled diff rows
// packed masked table: [b][p*32+m] = (rns[p][m], rns[p][m+32], -rnt[p][m], -rnt[p][m+32])
__device__ __align__(16) float4 g_rnTab4[BATCH][64*32];
__device__ double g_acc;
__device__ unsigned int g_done;

// ---------------------------------------------------------------- kernel 1
// Grid 128 = (b, t, s16). 64x64 Gram in-register from raw inputs, then rn +
// C rows for slice s (126 k-rows). rn written into the packed component of
// g_rnTab4 (negated for t==1); the (t==0,s==0) CTA zeroes invalid slots.
__global__ __launch_bounds__(256) void prep_k(const float* __restrict__ student,
                                              const float* __restrict__ teacher) {
    if (blockIdx.x == 0 && threadIdx.x == 0) { g_acc = 0.0; g_done = 0u; }
    int bid = blockIdx.x;
    int b = bid >> 5, t = (bid >> 4) & 1, s = bid & 15;
    const float* X = (t ? teacher : student) + (size_t)b * NPTS * DIM;

    __shared__ float sXT[32][67];
    __shared__ float G[64 * 64];
    __shared__ float sRNl[126];
    __shared__ int   sI[126], sJ[126];

    int tid = threadIdx.x;
    int bi = tid >> 4, bj = tid & 15;

    // zero invalid table slots (disjoint from all valid writes)
    if (t == 0 && s == 0) {
        for (int u = tid; u < 64 * 32; u += 256) {
            int p = u >> 5, m = u & 31;
            float* e = (float*)&g_rnTab4[b][u];
            if (m <= p || p == 63)      { e[0] = 0.f; e[2] = 0.f; }
            if (m + 32 <= p || p == 63) { e[1] = 0.f; e[3] = 0.f; }
        }
    }

    float acc[4][4];
    #pragma unroll
    for (int r = 0; r < 4; r++)
        #pragma unroll
        for (int c = 0; c < 4; c++) acc[r][c] = 0.f;

    for (int dq = 0; dq < 4; dq++) {
        if (dq) __syncthreads();
        for (int u = tid; u < NPTS * 32; u += 256) {
            int n = u >> 5, d = u & 31;
            sXT[d][n] = X[(size_t)n * DIM + dq * 32 + d];
        }
        __syncthreads();
        #pragma unroll 4
        for (int d = 0; d < 32; d++) {
            float xi[4], xj[4];
            #pragma unroll
            for (int r = 0; r < 4; r++) xi[r] = sXT[d][bi * 4 + r];
            #pragma unroll
            for (int c = 0; c < 4; c++) xj[c] = sXT[d][bj * 4 + c];
            #pragma unroll
            for (int r = 0; r < 4; r++)
                #pragma unroll
                for (int c = 0; c < 4; c++) acc[r][c] += xi[r] * xj[c];
        }
    }
    #pragma unroll
    for (int r = 0; r < 4; r++)
        #pragma unroll
        for (int c = 0; c < 4; c++)
            G[(bi * 4 + r) * 64 + (bj * 4 + c)] = acc[r][c];
    __syncthreads();

    if (tid < 126) {
        int l = s * 126 + tid;
        int p = 0, rem = l;
        while (rem >= 63 - p) { rem -= 63 - p; p++; }
        int q = p + 1 + rem;
        float ss = G[p * 64 + p] - 2.f * G[p * 64 + q] + G[q * 64 + q];
        float rn = 1.f / fmaxf(sqrtf(fmaxf(ss, 0.f)), 1e-12f);
        sI[tid] = p; sJ[tid] = q; sRNl[tid] = rn;
        // packed component: [q>=32] + 2*t ; negated for teacher
        ((float*)&g_rnTab4[b][p * 32 + (q & 31)])[(q >> 5) + 2 * t] = t ? -rn : rn;
    }
    __syncthreads();

    for (int u = tid; u < 126 * 64; u += 256) {
        int kl = u >> 6, p = u & 63;
        float val = (G[sI[kl] * 64 + p] - G[sJ[kl] * 64 + p]) * sRNl[kl];
        g_C[((size_t)(b * 2 + t) * NPRED + s * 126 + kl) * 64 + p] = val;
    }
}

// ---------------------------------------------------------------- kernel 2
// Grid 504 = (b, c126), 256 threads (8 warps). Warp w owns TWO k-rows:
// k0 = c*16 + w, k1 = c*16 + 8 + w — one table load feeds both. Full-square
// sum (table-masked; rn==0 kills q<=p). Constant 63-iteration unrolled loop.
__global__ __launch_bounds__(256) void loss_k(float* __restrict__ out) {
    __shared__ __align__(16) float4 sTab[64 * 32];   // 32 KB packed rn table
    __shared__ float wsum[8];

    int tid = threadIdx.x, wid = tid >> 5, lane = tid & 31;
    int bid = blockIdx.x;
    int b = bid / 126, c = bid - b * 126;

    {
        const float4* src = g_rnTab4[b];
        #pragma unroll
        for (int u = 0; u < 8; u++) sTab[tid + u * 256] = src[tid + u * 256];
    }
    __syncthreads();

    int k0 = c * 16 + wid;
    int k1 = c * 16 + 8 + wid;
    const float* Cs0 = g_C + ((size_t)(b * 2 + 0) * NPRED + k0) * 64;
    const float* Ct0 = g_C + ((size_t)(b * 2 + 1) * NPRED + k0) * 64;
    const float* Cs1 = g_C + ((size_t)(b * 2 + 0) * NPRED + k1) * 64;
    const float* Ct1 = g_C + ((size_t)(b * 2 + 1) * NPRED + k1) * 64;
    float s0a = Cs0[lane], s0b = Cs0[lane + 32];
    float t0a = Ct0[lane], t0b = Ct0[lane + 32];
    float s1a = Cs1[lane], s1b = Cs1[lane + 32];
    float t1a = Ct1[lane], t1b = Ct1[lane + 32];

    float acc0 = 0.f, acc1 = 0.f, acc2 = 0.f, acc3 = 0.f;
    #pragma unroll
    for (int p = 0; p < 63; p++) {
        float4 rl = sTab[p * 32 + lane];
        float cpS0 = __shfl_sync(0xffffffffu, (p < 32) ? s0a : s0b, p & 31);
        float cpT0 = __shfl_sync(0xffffffffu, (p < 32) ? t0a : t0b, p & 31);
        float cpS1 = __shfl_sync(0xffffffffu, (p < 32) ? s1a : s1b, p & 31);
        float cpT1 = __shfl_sync(0xffffffffu, (p < 32) ? t1a : t1b, p & 31);
        // k0, q = lane
        {
            float d = (cpS0 - s0a) * rl.x + (cpT0 - t0a) * rl.z;
            float a = fabsf(d), m = fminf(a, 1.f);
            acc0 += m * (a - 0.5f * m);
        }
        // k0, q = lane+32
        {
            float d = (cpS0 - s0b) * rl.y + (cpT0 - t0b) * rl.w;
            float a = fabsf(d), m = fminf(a, 1.f);
            acc1 += m * (a - 0.5f * m);
        }
        // k1, q = lane
        {
            float d = (cpS1 - s1a) * rl.x + (cpT1 - t1a) * rl.z;
            float a = fabsf(d), m = fminf(a, 1.f);
            acc2 += m * (a - 0.5f * m);
        }
        // k1, q = lane+32
        {
            float d = (cpS1 - s1b) * rl.y + (cpT1 - t1b) * rl.w;
            float a = fabsf(d), m = fminf(a, 1.f);
            acc3 += m * (a - 0.5f * m);
        }
    }

    float lsum = (acc0 + acc1) + (acc2 + acc3);
    #pragma unroll
    for (int o = 16; o; o >>= 1) lsum += __shfl_xor_sync(0xffffffffu, lsum, o);
    if (lane == 0) wsum[wid] = lsum;
    __syncthreads();
    if (tid == 0) {
        float sblk = 0.f;
        #pragma unroll
        for (int w2 = 0; w2 < 8; w2++) sblk += wsum[w2];
        atomicAdd(&g_acc, (double)sblk);
        __threadfence();
        unsigned int ticket = atomicAdd(&g_done, 1u);
        if (ticket == GRID_L - 1) {
            double v = *((volatile double*)&g_acc);
            out[0] = (float)(4.0 * v / ((double)BATCH * NFULL * NFULL));
        }
    }
}

extern "C" void kernel_launch(void* const* d_in, const int* in_sizes, int n_in,
                              void* d_out, int out_size) {
    const float* student = (const float*)d_in[0];
    const float* teacher = (const float*)d_in[1];
    prep_k<<<GRID_P, 256>>>(student, teacher);
    loss_k<<<GRID_L, 256>>>((float*)d_out);
}

// round 16
// speedup vs baseline: 1.4439x; 1.0537x over previous
#include <cuda_runtime.h>
#include <stdint.h>

#define BATCH  4
#define NPTS   64
#define DIM    128
#define NFULL  (NPTS*NPTS)     // 4096
#define NPRED  2016            // classes (i<j)
#define GRID_P 128             // (b, t, slice s of 126 rows)
#define GRID_L 1008            // (b, p-half, c126)

__device__ float g_C [(size_t)BATCH*2*NPRED*64];        // [b][t][k][p] scaled diff rows
// packed masked table: [b][p*32+m] = (rns[p][m], rns[p][m+32], -rnt[p][m], -rnt[p][m+32])
__device__ __align__(16) float4 g_rnTab4[BATCH][64*32];
__device__ double g_acc;
__device__ unsigned int g_done;

// ---------------------------------------------------------------- kernel 1
// Grid 128 = (b, t, s16). 64x64 Gram in-register from raw inputs, then rn +
// C rows for slice s (126 k-rows). rn written into the packed component of
// g_rnTab4 (negated for t==1); the (t==0,s==0) CTA zeroes invalid slots.
__global__ __launch_bounds__(256) void prep_k(const float* __restrict__ student,
                                              const float* __restrict__ teacher) {
    if (blockIdx.x == 0 && threadIdx.x == 0) { g_acc = 0.0; g_done = 0u; }
    int bid = blockIdx.x;
    int b = bid >> 5, t = (bid >> 4) & 1, s = bid & 15;
    const float* X = (t ? teacher : student) + (size_t)b * NPTS * DIM;

    __shared__ float sXT[32][67];
    __shared__ float G[64 * 64];
    __shared__ float sRNl[126];
    __shared__ int   sI[126], sJ[126];

    int tid = threadIdx.x;
    int bi = tid >> 4, bj = tid & 15;

    // zero invalid table slots (disjoint from all valid writes)
    if (t == 0 && s == 0) {
        for (int u = tid; u < 64 * 32; u += 256) {
            int p = u >> 5, m = u & 31;
            float* e = (float*)&g_rnTab4[b][u];
            if (m <= p || p == 63)      { e[0] = 0.f; e[2] = 0.f; }
            if (m + 32 <= p || p == 63) { e[1] = 0.f; e[3] = 0.f; }
        }
    }

    float acc[4][4];
    #pragma unroll
    for (int r = 0; r < 4; r++)
        #pragma unroll
        for (int c = 0; c < 4; c++) acc[r][c] = 0.f;

    for (int dq = 0; dq < 4; dq++) {
        if (dq) __syncthreads();
        for (int u = tid; u < NPTS * 32; u += 256) {
            int n = u >> 5, d = u & 31;
            sXT[d][n] = X[(size_t)n * DIM + dq * 32 + d];
        }
        __syncthreads();
        #pragma unroll 4
        for (int d = 0; d < 32; d++) {
            float xi[4], xj[4];
            #pragma unroll
            for (int r = 0; r < 4; r++) xi[r] = sXT[d][bi * 4 + r];
            #pragma unroll
            for (int c = 0; c < 4; c++) xj[c] = sXT[d][bj * 4 + c];
            #pragma unroll
            for (int r = 0; r < 4; r++)
                #pragma unroll
                for (int c = 0; c < 4; c++) acc[r][c] += xi[r] * xj[c];
        }
    }
    #pragma unroll
    for (int r = 0; r < 4; r++)
        #pragma unroll
        for (int c = 0; c < 4; c++)
            G[(bi * 4 + r) * 64 + (bj * 4 + c)] = acc[r][c];
    __syncthreads();

    if (tid < 126) {
        int l = s * 126 + tid;
        int p = 0, rem = l;
        while (rem >= 63 - p) { rem -= 63 - p; p++; }
        int q = p + 1 + rem;
        float ss = G[p * 64 + p] - 2.f * G[p * 64 + q] + G[q * 64 + q];
        float rn = 1.f / fmaxf(sqrtf(fmaxf(ss, 0.f)), 1e-12f);
        sI[tid] = p; sJ[tid] = q; sRNl[tid] = rn;
        // packed component: [q>=32] + 2*t ; negated for teacher
        ((float*)&g_rnTab4[b][p * 32 + (q & 31)])[(q >> 5) + 2 * t] = t ? -rn : rn;
    }
    __syncthreads();

    for (int u = tid; u < 126 * 64; u += 256) {
        int kl = u >> 6, p = u & 63;
        float val = (G[sI[kl] * 64 + p] - G[sJ[kl] * 64 + p]) * sRNl[kl];
        g_C[((size_t)(b * 2 + t) * NPRED + s * 126 + kl) * 64 + p] = val;
    }
}

// ---------------------------------------------------------------- kernel 2
// Grid 1008 = (b, ph, c126), 256 threads (8 warps). Warp w owns k-rows
// k0 = c*16 + w, k1 = c*16 + 8 + w; the p range is split in halves across
// CTAs (ph): each CTA runs a constant 32-iteration unrolled loop over
// p = ph*32 .. ph*32+31 (p==63 row is table-zeroed -> contributes 0).
// Per iteration: 1 broadcast LDS.128 (staged C values) + 1 LDS.128 (table),
// no shuffles. Full-square sum; reference loss = 4 * sum.
__global__ __launch_bounds__(256) void loss_k(float* __restrict__ out) {
    __shared__ __align__(16) float4 sTab[32 * 32];   // 16 KB half-table
    __shared__ __align__(16) float4 sCp[8][32];      // 4 KB per-warp broadcast rows
    __shared__ float wsum[8];

    int tid = threadIdx.x, wid = tid >> 5, lane = tid & 31;
    int bid = blockIdx.x;
    int b = bid / 252;
    int r = bid - b * 252;
    int ph = r / 126;
    int c = r - ph * 126;

    // copy half-table (rows p = ph*32 .. ph*32+31)
    {
        const float4* src = g_rnTab4[b] + ph * 32 * 32;
        #pragma unroll
        for (int u = 0; u < 4; u++) sTab[tid + u * 256] = src[tid + u * 256];
    }

    int k0 = c * 16 + wid;
    int k1 = c * 16 + 8 + wid;
    const float* Cs0 = g_C + ((size_t)(b * 2 + 0) * NPRED + k0) * 64;
    const float* Ct0 = g_C + ((size_t)(b * 2 + 1) * NPRED + k0) * 64;
    const float* Cs1 = g_C + ((size_t)(b * 2 + 0) * NPRED + k1) * 64;
    const float* Ct1 = g_C + ((size_t)(b * 2 + 1) * NPRED + k1) * 64;
    float s0a = Cs0[lane], s0b = Cs0[lane + 32];
    float t0a = Ct0[lane], t0b = Ct0[lane + 32];
    float s1a = Cs1[lane], s1b = Cs1[lane + 32];
    float t1a = Ct1[lane], t1b = Ct1[lane + 32];

    // stage this CTA's p-half of the C rows for broadcast reads
    sCp[wid][lane] = ph ? make_float4(s0b, t0b, s1b, t1b)
                        : make_float4(s0a, t0a, s1a, t1a);
    __syncthreads();

    float acc0 = 0.f, acc1 = 0.f, acc2 = 0.f, acc3 = 0.f;
    #pragma unroll
    for (int pp = 0; pp < 32; pp++) {
        float4 rl = sTab[pp * 32 + lane];
        float4 cp = sCp[wid][pp];      // uniform address -> broadcast
        // k0, q = lane
        {
            float d = (cp.x - s0a) * rl.x + (cp.y - t0a) * rl.z;
            float a = fabsf(d), m = fminf(a, 1.f);
            acc0 += m * (a - 0.5f * m);
        }
        // k0, q = lane+32
        {
            float d = (cp.x - s0b) * rl.y + (cp.y - t0b) * rl.w;
            float a = fabsf(d), m = fminf(a, 1.f);
            acc1 += m * (a - 0.5f * m);
        }
        // k1, q = lane
        {
            float d = (cp.z - s1a) * rl.x + (cp.w - t1a) * rl.z;
            float a = fabsf(d), m = fminf(a, 1.f);
            acc2 += m * (a - 0.5f * m);
        }
        // k1, q = lane+32
        {
            float d = (cp.z - s1b) * rl.y + (cp.w - t1b) * rl.w;
            float a = fabsf(d), m = fminf(a, 1.f);
            acc3 += m * (a - 0.5f * m);
        }
    }

    float lsum = (acc0 + acc1) + (acc2 + acc3);
    #pragma unroll
    for (int o = 16; o; o >>= 1) lsum += __shfl_xor_sync(0xffffffffu, lsum, o);
    if (lane == 0) wsum[wid] = lsum;
    __syncthreads();
    if (tid == 0) {
        float sblk = 0.f;
        #pragma unroll
        for (int w2 = 0; w2 < 8; w2++) sblk += wsum[w2];
        atomicAdd(&g_acc, (double)sblk);
        __threadfence();
        unsigned int ticket = atomicAdd(&g_done, 1u);
        if (ticket == GRID_L - 1) {
            double v = *((volatile double*)&g_acc);
            out[0] = (float)(4.0 * v / ((double)BATCH * NFULL * NFULL));
        }
    }
}

extern "C" void kernel_launch(void* const* d_in, const int* in_sizes, int n_in,
                              void* d_out, int out_size) {
    const float* student = (const float*)d_in[0];
    const float* teacher = (const float*)d_in[1];
    prep_k<<<GRID_P, 256>>>(student, teacher);
    loss_k<<<GRID_L, 256>>>((float*)d_out);
}